// round 11
// baseline (speedup 1.0000x reference)
#include <cuda_runtime.h>
#include <cuda_fp16.h>
#include <cstdint>
#include <math.h>

#define BATCH 8
#define NOBS 1024
#define MOUT 1024
#define CCH 16
#define OCH 32
#define THREADS 512
#define M_B 16                   // m per block
#define MTILES (MOUT / M_B)      // 64 -> grid 512
#define KSPLIT 16
#define KPW (NOBS / KSPLIT)      // 64 per warp
#define KTILES (KPW / 16)        // 4 k-tiles
#define ROWH 24                  // halves per y row: 16 data + 8 pad = 48B
#define ROWB (ROWH * 2)          // 48 bytes

__device__ __forceinline__ float ex2f(float v) {
    float r; asm("ex2.approx.ftz.f32 %0, %1;" : "=f"(r) : "f"(v)); return r;
}
__device__ __forceinline__ uint32_t s2u(const void* p) {
    return (uint32_t)__cvta_generic_to_shared(p);
}
__device__ __forceinline__ uint32_t packh2(float lo, float hi) {
    uint32_t r; asm("cvt.rn.f16x2.f32 %0, %1, %2;" : "=r"(r) : "f"(hi), "f"(lo)); return r;
}
__device__ __forceinline__ void ldm_x4_t(uint32_t& r0, uint32_t& r1, uint32_t& r2,
                                         uint32_t& r3, uint32_t addr) {
    asm volatile("ldmatrix.sync.aligned.m8n8.x4.trans.shared.b16 {%0,%1,%2,%3}, [%4];"
                 : "=r"(r0), "=r"(r1), "=r"(r2), "=r"(r3) : "r"(addr));
}
__device__ __forceinline__ void mma16816(float& c0, float& c1, float& c2, float& c3,
                                         uint32_t a0, uint32_t a1, uint32_t a2, uint32_t a3,
                                         uint32_t b0, uint32_t b1) {
    asm volatile("mma.sync.aligned.m16n8k16.row.col.f32.f16.f16.f32 "
                 "{%0,%1,%2,%3}, {%4,%5,%6,%7}, {%8,%9}, {%0,%1,%2,%3};"
                 : "+f"(c0), "+f"(c1), "+f"(c2), "+f"(c3)
                 : "r"(a0), "r"(a1), "r"(a2), "r"(a3), "r"(b0), "r"(b1));
}

struct SMem {
    float  sx[NOBS];                        // 4 KB (scaled by s in uniform mode)
    __align__(16) __half syh[NOBS][ROWH];   // 48 KB single f16 plane
    float  sred[KSPLIT][M_B][CCH];          // 16 KB
};
#define DYN_SMEM_BYTES ((int)sizeof(SMem))

__global__ __launch_bounds__(THREADS, 2) void setconv_mma_kernel(
    const float* __restrict__ x, const float* __restrict__ y,
    const float* __restrict__ t, const float* __restrict__ sigma,
    const float* __restrict__ W, const float* __restrict__ bias,
    float* __restrict__ out)
{
    extern __shared__ __align__(16) unsigned char dynsm[];
    SMem& u = *reinterpret_cast<SMem*>(dynsm);
    __shared__ float sWt[CCH][OCH];
    __shared__ float sb[OCH];
    __shared__ float yout[M_B][CCH + 1];

    const int tid  = threadIdx.x;
    const int warp = tid >> 5, lane = tid & 31;
    const int b  = blockIdx.x / MTILES;
    const int mt = blockIdx.x % MTILES;
    const int mbase = mt * M_B;
    const int ks = warp;            // k-split 0..15 (64 n each)

    const float sg0 = sigma[0];
    bool uniform = true;
    #pragma unroll
    for (int c = 1; c < CCH; c++) uniform &= (sigma[c] == sg0);
    // q0 = -0.5*log2(e)/s^2; scl = sqrt(-q0) so exp2(q0*d^2) = exp2(-(scl*d)^2)
    const float q0  = -0.72134752044448170f * ex2f(-2.0f * sg0 * 1.4426950408889634f);
    const float scl = sqrtf(-q0);

    // ---- stage x (scaled), y (f16), W, bias ----
    {
        const float xs = uniform ? scl : 1.0f;
        for (int i = tid; i < NOBS; i += THREADS)
            u.sx[i] = xs * x[b * NOBS + i];
    }
    {
        const float4* yb = (const float4*)(y + (size_t)b * NOBS * CCH);
        #pragma unroll
        for (int r = 0; r < NOBS * CCH / 4 / THREADS; r++) {   // 8 rounds
            int j = tid + THREADS * r;
            int n = j >> 2, c4 = j & 3;
            float4 v = yb[j];
            uint2 pk;
            pk.x = packh2(v.x, v.y);
            pk.y = packh2(v.z, v.w);
            *(uint2*)&u.syh[n][c4 * 4] = pk;
        }
    }
    for (int i = tid; i < OCH * CCH; i += THREADS) {
        int o = i / CCH, c = i % CCH;
        sWt[c][o] = W[i];
    }
    if (tid < OCH) sb[tid] = bias[tid];

    __syncthreads();

    if (uniform) {
        const int g  = lane >> 2;        // 0..7
        const int tq = lane & 3;         // 0..3
        const float t0 = scl * t[b * MOUT + mbase + g];
        const float t1 = scl * t[b * MOUT + mbase + g + 8];

        float c00 = 0.f, c01 = 0.f, c02 = 0.f, c03 = 0.f;   // ch0-7
        float c10 = 0.f, c11 = 0.f, c12 = 0.f, c13 = 0.f;   // ch8-15

        const int kbase = ks * KPW;
        const float* sxw = &u.sx[kbase + 2 * tq];
        const uint32_t lmw = s2u(&u.syh[kbase + (lane & 15)][0])
                           + ((lane & 16) ? 16u : 0u);

        // prologue: prefetch ktile 0
        float2 xa = *(const float2*)&sxw[0];
        float2 xb = *(const float2*)&sxw[8];
        uint32_t bh[4];
        ldm_x4_t(bh[0], bh[1], bh[2], bh[3], lmw);

        #pragma unroll
        for (int kt = 0; kt < KTILES; kt++) {
            float2 nxa, nxb;
            uint32_t nbh[4];
            if (kt + 1 < KTILES) {
                nxa = *(const float2*)&sxw[(kt + 1) * 16];
                nxb = *(const float2*)&sxw[(kt + 1) * 16 + 8];
                ldm_x4_t(nbh[0], nbh[1], nbh[2], nbh[3],
                         lmw + (uint32_t)(kt + 1) * (16 * ROWB));
            }

            float d;
            d = xa.x - t0; const float w00 = ex2f(-d * d);
            d = xa.y - t0; const float w01 = ex2f(-d * d);
            d = xa.x - t1; const float w10 = ex2f(-d * d);
            d = xa.y - t1; const float w11 = ex2f(-d * d);
            d = xb.x - t0; const float w02 = ex2f(-d * d);
            d = xb.y - t0; const float w03 = ex2f(-d * d);
            d = xb.x - t1; const float w12 = ex2f(-d * d);
            d = xb.y - t1; const float w13 = ex2f(-d * d);

            const uint32_t a0 = packh2(w00, w01);
            const uint32_t a1 = packh2(w10, w11);
            const uint32_t a2 = packh2(w02, w03);
            const uint32_t a3 = packh2(w12, w13);

            mma16816(c00, c01, c02, c03, a0, a1, a2, a3, bh[0], bh[1]);
            mma16816(c10, c11, c12, c13, a0, a1, a2, a3, bh[2], bh[3]);

            xa = nxa; xb = nxb;
            #pragma unroll
            for (int j = 0; j < 4; j++) bh[j] = nbh[j];
        }

        // sred distinct region: no barrier needed before writing
        const int col0 = 2 * tq;
        *(float2*)&u.sred[ks][g][col0]           = make_float2(c00, c01);
        *(float2*)&u.sred[ks][g + 8][col0]       = make_float2(c02, c03);
        *(float2*)&u.sred[ks][g][8 + col0]       = make_float2(c10, c11);
        *(float2*)&u.sred[ks][g + 8][8 + col0]   = make_float2(c12, c13);
    } else {
        // ---- general per-channel-sigma fallback (slow, correct) ----
        float q[CCH];
        #pragma unroll
        for (int c = 0; c < CCH; c++)
            q[c] = -0.72134752044448170f * ex2f(-2.0f * sigma[c] * 1.4426950408889634f);
        const int ml = lane & 15;
        const int half = lane >> 4;
        const float tm = t[b * MOUT + mbase + ml];
        float acc[CCH];
        #pragma unroll
        for (int c = 0; c < CCH; c++) acc[c] = 0.0f;
        for (int nn = ks * KPW + half; nn < (ks + 1) * KPW; nn += 2) {
            const float xv = u.sx[nn];
            const float dd = (xv - tm) * (xv - tm);
            const __half2* row = (const __half2*)&u.syh[nn][0];
            #pragma unroll
            for (int c2 = 0; c2 < 8; c2++) {
                const float2 yh = __half22float2(row[c2]);
                acc[2 * c2]     += ex2f(q[2 * c2] * dd) * yh.x;
                acc[2 * c2 + 1] += ex2f(q[2 * c2 + 1] * dd) * yh.y;
            }
        }
        #pragma unroll
        for (int c = 0; c < CCH; c++)
            acc[c] += __shfl_xor_sync(0xffffffffu, acc[c], 16);
        if (half == 0)
            #pragma unroll
            for (int c = 0; c < CCH; c++) u.sred[ks][ml][c] = acc[c];
    }

    __syncthreads();

    // ---- reduce 16 k-splits -> yout (256 sums; threads 0..255) ----
    if (tid < M_B * CCH) {
        const int m = tid >> 4;        // 0..15
        const int c = tid & 15;
        float s = 0.0f;
        #pragma unroll
        for (int k = 0; k < KSPLIT; k++) s += u.sred[k][m][c];
        yout[m][c] = s;
    }
    __syncthreads();

    // ---- 16->32 linear: thread = (o, m); W once/lane, yout warp-broadcast ----
    {
        const int o = tid & 31;         // distinct per lane
        const int m = tid >> 5;         // 0..15, constant within warp
        float a = sb[o];
        #pragma unroll
        for (int c = 0; c < CCH; c++) a += yout[m][c] * sWt[c][o];
        out[((size_t)b * MOUT + mbase + m) * OCH + o] = a;
    }
}

extern "C" void kernel_launch(void* const* d_in, const int* in_sizes, int n_in,
                              void* d_out, int out_size)
{
    const float* x     = (const float*)d_in[0];
    const float* y     = (const float*)d_in[1];
    const float* t     = (const float*)d_in[2];
    const float* sigma = (const float*)d_in[3];
    const float* W     = (const float*)d_in[4];
    const float* bias  = (const float*)d_in[5];
    float* out = (float*)d_out;

    cudaFuncSetAttribute(setconv_mma_kernel,
                         cudaFuncAttributeMaxDynamicSharedMemorySize, DYN_SMEM_BYTES);
    setconv_mma_kernel<<<BATCH * MTILES, THREADS, DYN_SMEM_BYTES>>>(
        x, y, t, sigma, W, bias, out);
}

// round 13
// speedup vs baseline: 1.1538x; 1.1538x over previous
#include <cuda_runtime.h>
#include <cuda_fp16.h>
#include <cstdint>
#include <math.h>

#define BATCH 8
#define NOBS 1024
#define MOUT 1024
#define CCH 16
#define OCH 32
#define THREADS 512
#define M_B 16                   // m per block
#define MTILES (MOUT / M_B)      // 64 -> grid 512
#define KSPLIT 16
#define KTG 64                   // global k-tiles of 16 obs
#define KT_PER_WARP (KTG / KSPLIT)  // 4

// Precomputed MMA fragments (written by build_frags, read by main kernel)
__device__ uint4  g_bf[BATCH][KTG][32];   // B fragments: y as f16, 256 KB
__device__ float4 g_xf[BATCH][KTG][32];   // x values per lane, 256 KB

__device__ __forceinline__ float ex2f(float v) {
    float r; asm("ex2.approx.ftz.f32 %0, %1;" : "=f"(r) : "f"(v)); return r;
}
__device__ __forceinline__ uint32_t packh2(float lo, float hi) {
    uint32_t r; asm("cvt.rn.f16x2.f32 %0, %1, %2;" : "=r"(r) : "f"(hi), "f"(lo)); return r;
}
__device__ __forceinline__ void mma16816(float& c0, float& c1, float& c2, float& c3,
                                         uint32_t a0, uint32_t a1, uint32_t a2, uint32_t a3,
                                         uint32_t b0, uint32_t b1) {
    asm volatile("mma.sync.aligned.m16n8k16.row.col.f32.f16.f16.f32 "
                 "{%0,%1,%2,%3}, {%4,%5,%6,%7}, {%8,%9}, {%0,%1,%2,%3};"
                 : "+f"(c0), "+f"(c1), "+f"(c2), "+f"(c3)
                 : "r"(a0), "r"(a1), "r"(a2), "r"(a3), "r"(b0), "r"(b1));
}

__device__ __forceinline__ bool sigma_uniform(const float* sigma, float& sg0) {
    sg0 = sigma[0];
    bool u = true;
    #pragma unroll
    for (int c = 1; c < CCH; c++) u &= (sigma[c] == sg0);
    return u;
}

// ---- kernel 1: build B (y->f16 fragment) and x fragments ----
__global__ __launch_bounds__(256) void build_frags(
    const float* __restrict__ x, const float* __restrict__ y,
    const float* __restrict__ sigma)
{
    const int idx = blockIdx.x * 256 + threadIdx.x;   // 0..16383
    const int b  = idx >> 11;           // / (KTG*32)
    const int kt = (idx >> 5) & (KTG - 1);
    const int l  = idx & 31;
    const int q  = l & 3, c = l >> 2;
    const int k0 = kt * 16;

    float sg0;
    const bool uni = sigma_uniform(sigma, sg0);
    const float q0  = -0.72134752044448170f * ex2f(-2.0f * sg0 * 1.4426950408889634f);
    const float scl = uni ? sqrtf(-q0) : 1.0f;

    const float* yb = y + (size_t)b * NOBS * CCH;
    uint4 bf;
    bf.x = packh2(yb[(k0 + 2*q) * CCH + c],         yb[(k0 + 2*q + 1) * CCH + c]);
    bf.y = packh2(yb[(k0 + 8 + 2*q) * CCH + c],     yb[(k0 + 9 + 2*q) * CCH + c]);
    bf.z = packh2(yb[(k0 + 2*q) * CCH + c + 8],     yb[(k0 + 2*q + 1) * CCH + c + 8]);
    bf.w = packh2(yb[(k0 + 8 + 2*q) * CCH + c + 8], yb[(k0 + 9 + 2*q) * CCH + c + 8]);
    g_bf[b][kt][l] = bf;

    const float* xb = x + b * NOBS;
    g_xf[b][kt][l] = make_float4(scl * xb[k0 + 2*q],     scl * xb[k0 + 2*q + 1],
                                 scl * xb[k0 + 8 + 2*q], scl * xb[k0 + 9 + 2*q]);
}

// ---- kernel 2: mainloop straight from fragments; no staging ----
__global__ __launch_bounds__(THREADS, 2) void setconv_mma_kernel(
    const float* __restrict__ x, const float* __restrict__ y,
    const float* __restrict__ t, const float* __restrict__ sigma,
    const float* __restrict__ W, const float* __restrict__ bias,
    float* __restrict__ out)
{
    __shared__ float sred[KSPLIT][M_B][CCH];   // 16 KB
    __shared__ float yout[M_B][CCH + 1];
    __shared__ float sWt[CCH][OCH];
    __shared__ float sb[OCH];

    const int tid  = threadIdx.x;
    const int warp = tid >> 5, lane = tid & 31;
    const int b  = blockIdx.x / MTILES;
    const int mt = blockIdx.x % MTILES;
    const int mbase = mt * M_B;
    const int ks = warp;                 // k-split 0..15, 4 ktiles each

    for (int i = tid; i < OCH * CCH; i += THREADS) {
        int o = i / CCH, c = i % CCH;
        sWt[c][o] = W[i];
    }
    if (tid < OCH) sb[tid] = bias[tid];

    float sg0;
    const bool uniform = sigma_uniform(sigma, sg0);
    const float q0  = -0.72134752044448170f * ex2f(-2.0f * sg0 * 1.4426950408889634f);
    const float scl = sqrtf(-q0);

    if (uniform) {
        const int g = lane >> 2;         // 0..7
        const float t0 = scl * t[b * MOUT + mbase + g];
        const float t1 = scl * t[b * MOUT + mbase + g + 8];

        float c00 = 0.f, c01 = 0.f, c02 = 0.f, c03 = 0.f;   // ch0-7
        float c10 = 0.f, c11 = 0.f, c12 = 0.f, c13 = 0.f;   // ch8-15

        const uint4*  bfp = &g_bf[b][ks * KT_PER_WARP][lane];
        const float4* xfp = &g_xf[b][ks * KT_PER_WARP][lane];

        // prologue: prefetch ktile 0
        uint4  bf = bfp[0];
        float4 xf = xfp[0];

        #pragma unroll
        for (int kt = 0; kt < KT_PER_WARP; kt++) {
            uint4  nbf;
            float4 nxf;
            if (kt + 1 < KT_PER_WARP) {
                nbf = bfp[(kt + 1) * 32];
                nxf = xfp[(kt + 1) * 32];
            }

            float d;
            d = xf.x - t0; const float w00 = ex2f(-d * d);
            d = xf.y - t0; const float w01 = ex2f(-d * d);
            d = xf.x - t1; const float w10 = ex2f(-d * d);
            d = xf.y - t1; const float w11 = ex2f(-d * d);
            d = xf.z - t0; const float w02 = ex2f(-d * d);
            d = xf.w - t0; const float w03 = ex2f(-d * d);
            d = xf.z - t1; const float w12 = ex2f(-d * d);
            d = xf.w - t1; const float w13 = ex2f(-d * d);

            const uint32_t a0 = packh2(w00, w01);
            const uint32_t a1 = packh2(w10, w11);
            const uint32_t a2 = packh2(w02, w03);
            const uint32_t a3 = packh2(w12, w13);

            mma16816(c00, c01, c02, c03, a0, a1, a2, a3, bf.x, bf.y);
            mma16816(c10, c11, c12, c13, a0, a1, a2, a3, bf.z, bf.w);

            bf = nbf; xf = nxf;
        }

        const int tq = lane & 3;
        const int col0 = 2 * tq;
        *(float2*)&sred[ks][g][col0]          = make_float2(c00, c01);
        *(float2*)&sred[ks][g + 8][col0]      = make_float2(c02, c03);
        *(float2*)&sred[ks][g][8 + col0]      = make_float2(c10, c11);
        *(float2*)&sred[ks][g + 8][8 + col0]  = make_float2(c12, c13);
    } else {
        // ---- general per-channel-sigma fallback (slow, correct; global reads) ----
        float q[CCH];
        #pragma unroll
        for (int c = 0; c < CCH; c++)
            q[c] = -0.72134752044448170f * ex2f(-2.0f * sigma[c] * 1.4426950408889634f);
        const int ml = lane & 15;
        const int half = lane >> 4;
        const float tm = t[b * MOUT + mbase + ml];
        float acc[CCH];
        #pragma unroll
        for (int c = 0; c < CCH; c++) acc[c] = 0.0f;
        const int n0 = ks * (NOBS / KSPLIT);
        for (int nn = n0 + half; nn < n0 + NOBS / KSPLIT; nn += 2) {
            const float xv = x[b * NOBS + nn];
            const float dd = (xv - tm) * (xv - tm);
            const float* yr = y + ((size_t)b * NOBS + nn) * CCH;
            #pragma unroll
            for (int c = 0; c < CCH; c++)
                acc[c] += ex2f(q[c] * dd) * yr[c];
        }
        #pragma unroll
        for (int c = 0; c < CCH; c++)
            acc[c] += __shfl_xor_sync(0xffffffffu, acc[c], 16);
        if (half == 0)
            #pragma unroll
            for (int c = 0; c < CCH; c++) sred[ks][ml][c] = acc[c];
    }

    __syncthreads();

    // ---- reduce 16 k-splits -> yout (256 sums; threads 0..255) ----
    if (tid < M_B * CCH) {
        const int m = tid >> 4;        // 0..15
        const int c = tid & 15;
        float s = 0.0f;
        #pragma unroll
        for (int k = 0; k < KSPLIT; k++) s += sred[k][m][c];
        yout[m][c] = s;
    }
    __syncthreads();

    // ---- 16->32 linear: thread = (o, m); W once/lane, yout warp-broadcast ----
    {
        const int o = tid & 31;         // distinct per lane
        const int m = tid >> 5;         // 0..15, constant within warp
        float a = sb[o];
        #pragma unroll
        for (int c = 0; c < CCH; c++) a += yout[m][c] * sWt[c][o];
        out[((size_t)b * MOUT + mbase + m) * OCH + o] = a;
    }
}

extern "C" void kernel_launch(void* const* d_in, const int* in_sizes, int n_in,
                              void* d_out, int out_size)
{
    const float* x     = (const float*)d_in[0];
    const float* y     = (const float*)d_in[1];
    const float* t     = (const float*)d_in[2];
    const float* sigma = (const float*)d_in[3];
    const float* W     = (const float*)d_in[4];
    const float* bias  = (const float*)d_in[5];
    float* out = (float*)d_out;

    build_frags<<<BATCH * KTG * 32 / 256, 256>>>(x, y, sigma);
    setconv_mma_kernel<<<BATCH * MTILES, THREADS>>>(x, y, t, sigma, W, bias, out);
}

// round 15
// speedup vs baseline: 1.1658x; 1.0104x over previous
#include <cuda_runtime.h>
#include <cuda_fp16.h>
#include <cstdint>
#include <math.h>

#define BATCH 8
#define NOBS 1024
#define MOUT 1024
#define CCH 16
#define OCH 32
#define THREADS 128              // 4 warps per block
#define M_B 16                   // m per block
#define MTILES (MOUT / M_B)      // 64 -> grid 512
#define KSPLIT 4
#define KTG 64                   // global k-tiles of 16 obs
#define KT_PER_WARP (KTG / KSPLIT)  // 16

// Precomputed MMA fragments (written by build_frags, read by main kernel)
__device__ uint4  g_bf[BATCH][KTG][32];   // B fragments: y as f16, 256 KB
__device__ float4 g_xf[BATCH][KTG][32];   // x values per lane, 256 KB

__device__ __forceinline__ float ex2f(float v) {
    float r; asm("ex2.approx.ftz.f32 %0, %1;" : "=f"(r) : "f"(v)); return r;
}
__device__ __forceinline__ uint32_t packh2(float lo, float hi) {
    uint32_t r; asm("cvt.rn.f16x2.f32 %0, %1, %2;" : "=r"(r) : "f"(hi), "f"(lo)); return r;
}
__device__ __forceinline__ void mma16816(float& c0, float& c1, float& c2, float& c3,
                                         uint32_t a0, uint32_t a1, uint32_t a2, uint32_t a3,
                                         uint32_t b0, uint32_t b1) {
    asm volatile("mma.sync.aligned.m16n8k16.row.col.f32.f16.f16.f32 "
                 "{%0,%1,%2,%3}, {%4,%5,%6,%7}, {%8,%9}, {%0,%1,%2,%3};"
                 : "+f"(c0), "+f"(c1), "+f"(c2), "+f"(c3)
                 : "r"(a0), "r"(a1), "r"(a2), "r"(a3), "r"(b0), "r"(b1));
}

__device__ __forceinline__ bool sigma_uniform(const float* sigma, float& sg0) {
    sg0 = sigma[0];
    bool u = true;
    #pragma unroll
    for (int c = 1; c < CCH; c++) u &= (sigma[c] == sg0);
    return u;
}

// ---- kernel 1: build B (y->f16 fragment) and x fragments ----
__global__ __launch_bounds__(256) void build_frags(
    const float* __restrict__ x, const float* __restrict__ y,
    const float* __restrict__ sigma)
{
    const int idx = blockIdx.x * 256 + threadIdx.x;   // 0..16383
    const int b  = idx >> 11;           // / (KTG*32)
    const int kt = (idx >> 5) & (KTG - 1);
    const int l  = idx & 31;
    const int q  = l & 3, c = l >> 2;
    const int k0 = kt * 16;

    float sg0;
    const bool uni = sigma_uniform(sigma, sg0);
    const float q0  = -0.72134752044448170f * ex2f(-2.0f * sg0 * 1.4426950408889634f);
    const float scl = uni ? sqrtf(-q0) : 1.0f;

    const float* yb = y + (size_t)b * NOBS * CCH;
    uint4 bf;
    bf.x = packh2(yb[(k0 + 2*q) * CCH + c],         yb[(k0 + 2*q + 1) * CCH + c]);
    bf.y = packh2(yb[(k0 + 8 + 2*q) * CCH + c],     yb[(k0 + 9 + 2*q) * CCH + c]);
    bf.z = packh2(yb[(k0 + 2*q) * CCH + c + 8],     yb[(k0 + 2*q + 1) * CCH + c + 8]);
    bf.w = packh2(yb[(k0 + 8 + 2*q) * CCH + c + 8], yb[(k0 + 9 + 2*q) * CCH + c + 8]);
    g_bf[b][kt][l] = bf;

    const float* xb = x + b * NOBS;
    g_xf[b][kt][l] = make_float4(scl * xb[k0 + 2*q],     scl * xb[k0 + 2*q + 1],
                                 scl * xb[k0 + 8 + 2*q], scl * xb[k0 + 9 + 2*q]);
}

// ---- kernel 2: mainloop straight from fragments; no staging ----
__global__ __launch_bounds__(THREADS) void setconv_mma_kernel(
    const float* __restrict__ x, const float* __restrict__ y,
    const float* __restrict__ t, const float* __restrict__ sigma,
    const float* __restrict__ W, const float* __restrict__ bias,
    float* __restrict__ out)
{
    __shared__ float sred[KSPLIT][M_B][CCH];   // 4 KB
    __shared__ float yout[M_B][CCH + 1];
    __shared__ float sWt[CCH][OCH];
    __shared__ float sb[OCH];

    const int tid  = threadIdx.x;
    const int warp = tid >> 5, lane = tid & 31;
    const int b  = blockIdx.x / MTILES;
    const int mt = blockIdx.x % MTILES;
    const int mbase = mt * M_B;
    const int ks = warp;                 // k-split 0..3, 16 ktiles each

    for (int i = tid; i < OCH * CCH; i += THREADS) {
        int o = i / CCH, c = i % CCH;
        sWt[c][o] = W[i];
    }
    if (tid < OCH) sb[tid] = bias[tid];

    float sg0;
    const bool uniform = sigma_uniform(sigma, sg0);
    const float q0  = -0.72134752044448170f * ex2f(-2.0f * sg0 * 1.4426950408889634f);
    const float scl = sqrtf(-q0);

    if (uniform) {
        const int g = lane >> 2;         // 0..7
        const float t0 = scl * t[b * MOUT + mbase + g];
        const float t1 = scl * t[b * MOUT + mbase + g + 8];

        float c00 = 0.f, c01 = 0.f, c02 = 0.f, c03 = 0.f;   // ch0-7
        float c10 = 0.f, c11 = 0.f, c12 = 0.f, c13 = 0.f;   // ch8-15

        const uint4*  bfp = &g_bf[b][ks * KT_PER_WARP][lane];
        const float4* xfp = &g_xf[b][ks * KT_PER_WARP][lane];

        // prologue: prefetch ktile 0
        uint4  bf = bfp[0];
        float4 xf = xfp[0];

        #pragma unroll 4
        for (int kt = 0; kt < KT_PER_WARP; kt++) {
            uint4  nbf;
            float4 nxf;
            if (kt + 1 < KT_PER_WARP) {
                nbf = bfp[(kt + 1) * 32];
                nxf = xfp[(kt + 1) * 32];
            }

            float d;
            d = xf.x - t0; const float w00 = ex2f(-d * d);
            d = xf.y - t0; const float w01 = ex2f(-d * d);
            d = xf.x - t1; const float w10 = ex2f(-d * d);
            d = xf.y - t1; const float w11 = ex2f(-d * d);
            d = xf.z - t0; const float w02 = ex2f(-d * d);
            d = xf.w - t0; const float w03 = ex2f(-d * d);
            d = xf.z - t1; const float w12 = ex2f(-d * d);
            d = xf.w - t1; const float w13 = ex2f(-d * d);

            const uint32_t a0 = packh2(w00, w01);
            const uint32_t a1 = packh2(w10, w11);
            const uint32_t a2 = packh2(w02, w03);
            const uint32_t a3 = packh2(w12, w13);

            mma16816(c00, c01, c02, c03, a0, a1, a2, a3, bf.x, bf.y);
            mma16816(c10, c11, c12, c13, a0, a1, a2, a3, bf.z, bf.w);

            bf = nbf; xf = nxf;
        }

        const int tq = lane & 3;
        const int col0 = 2 * tq;
        *(float2*)&sred[ks][g][col0]          = make_float2(c00, c01);
        *(float2*)&sred[ks][g + 8][col0]      = make_float2(c02, c03);
        *(float2*)&sred[ks][g][8 + col0]      = make_float2(c10, c11);
        *(float2*)&sred[ks][g + 8][8 + col0]  = make_float2(c12, c13);
    } else {
        // ---- general per-channel-sigma fallback (slow, correct; global reads) ----
        float q[CCH];
        #pragma unroll
        for (int c = 0; c < CCH; c++)
            q[c] = -0.72134752044448170f * ex2f(-2.0f * sigma[c] * 1.4426950408889634f);
        const int ml = lane & 15;
        const int half = lane >> 4;
        const float tm = t[b * MOUT + mbase + ml];
        float acc[CCH];
        #pragma unroll
        for (int c = 0; c < CCH; c++) acc[c] = 0.0f;
        const int n0 = ks * (NOBS / KSPLIT);
        for (int nn = n0 + half; nn < n0 + NOBS / KSPLIT; nn += 2) {
            const float xv = x[b * NOBS + nn];
            const float dd = (xv - tm) * (xv - tm);
            const float* yr = y + ((size_t)b * NOBS + nn) * CCH;
            #pragma unroll
            for (int c = 0; c < CCH; c++)
                acc[c] += ex2f(q[c] * dd) * yr[c];
        }
        #pragma unroll
        for (int c = 0; c < CCH; c++)
            acc[c] += __shfl_xor_sync(0xffffffffu, acc[c], 16);
        if (half == 0)
            #pragma unroll
            for (int c = 0; c < CCH; c++) sred[ks][ml][c] = acc[c];
    }

    __syncthreads();

    // ---- reduce 4 k-splits -> yout (256 sums; 2 per thread) ----
    #pragma unroll
    for (int r = 0; r < 2; r++) {
        const int idx = tid + THREADS * r;   // 0..255
        const int m = idx >> 4;
        const int c = idx & 15;
        float s = 0.0f;
        #pragma unroll
        for (int k = 0; k < KSPLIT; k++) s += sred[k][m][c];
        yout[m][c] = s;
    }
    __syncthreads();

    // ---- 16->32 linear: thread = (o, m-group); 4 m per thread, coalesced ----
    {
        const int o  = tid & 31;        // distinct per lane
        const int mg = tid >> 5;        // 0..3, constant within warp
        const float bv = sb[o];
        float wv[CCH];
        #pragma unroll
        for (int c = 0; c < CCH; c++) wv[c] = sWt[c][o];
        #pragma unroll
        for (int j = 0; j < 4; j++) {
            const int m = mg * 4 + j;
            float a = bv;
            #pragma unroll
            for (int c = 0; c < CCH; c++) a += yout[m][c] * wv[c];
            out[((size_t)b * MOUT + mbase + m) * OCH + o] = a;
        }
    }
}

extern "C" void kernel_launch(void* const* d_in, const int* in_sizes, int n_in,
                              void* d_out, int out_size)
{
    const float* x     = (const float*)d_in[0];
    const float* y     = (const float*)d_in[1];
    const float* t     = (const float*)d_in[2];
    const float* sigma = (const float*)d_in[3];
    const float* W     = (const float*)d_in[4];
    const float* bias  = (const float*)d_in[5];
    float* out = (float*)d_out;

    build_frags<<<BATCH * KTG * 32 / 256, 256>>>(x, y, sigma);
    setconv_mma_kernel<<<BATCH * MTILES, THREADS>>>(x, y, t, sigma, W, bias, out);
}

// round 16
// speedup vs baseline: 1.1688x; 1.0026x over previous
#include <cuda_runtime.h>
#include <cuda_fp16.h>
#include <cstdint>
#include <math.h>

#define BATCH 8
#define NOBS 1024
#define MOUT 1024
#define CCH 16
#define OCH 32
#define THREADS 256              // 8 warps per block
#define M_B 16                   // m per block
#define MTILES (MOUT / M_B)      // 64 -> grid 512
#define KSPLIT 8
#define KTG 64                   // global k-tiles of 16 obs
#define KT_PER_WARP (KTG / KSPLIT)  // 8
#define CHUNK 4                  // k-tiles per load burst
#define NCHUNKS (KT_PER_WARP / CHUNK) // 2

// Precomputed MMA fragments (written by build_frags, read by main kernel)
__device__ uint4  g_bf[BATCH][KTG][32];   // B fragments: y as f16, 256 KB
__device__ float4 g_xf[BATCH][KTG][32];   // x values per lane, 256 KB

__device__ __forceinline__ float ex2f(float v) {
    float r; asm("ex2.approx.ftz.f32 %0, %1;" : "=f"(r) : "f"(v)); return r;
}
__device__ __forceinline__ uint32_t packh2(float lo, float hi) {
    uint32_t r; asm("cvt.rn.f16x2.f32 %0, %1, %2;" : "=r"(r) : "f"(hi), "f"(lo)); return r;
}
__device__ __forceinline__ void mma16816(float& c0, float& c1, float& c2, float& c3,
                                         uint32_t a0, uint32_t a1, uint32_t a2, uint32_t a3,
                                         uint32_t b0, uint32_t b1) {
    asm volatile("mma.sync.aligned.m16n8k16.row.col.f32.f16.f16.f32 "
                 "{%0,%1,%2,%3}, {%4,%5,%6,%7}, {%8,%9}, {%0,%1,%2,%3};"
                 : "+f"(c0), "+f"(c1), "+f"(c2), "+f"(c3)
                 : "r"(a0), "r"(a1), "r"(a2), "r"(a3), "r"(b0), "r"(b1));
}

__device__ __forceinline__ bool sigma_uniform(const float* sigma, float& sg0) {
    sg0 = sigma[0];
    bool u = true;
    #pragma unroll
    for (int c = 1; c < CCH; c++) u &= (sigma[c] == sg0);
    return u;
}

// ---- kernel 1: build B (y->f16 fragment) and x fragments ----
__global__ __launch_bounds__(256) void build_frags(
    const float* __restrict__ x, const float* __restrict__ y,
    const float* __restrict__ sigma)
{
    const int idx = blockIdx.x * 256 + threadIdx.x;   // 0..16383
    const int b  = idx >> 11;           // / (KTG*32)
    const int kt = (idx >> 5) & (KTG - 1);
    const int l  = idx & 31;
    const int q  = l & 3, c = l >> 2;
    const int k0 = kt * 16;

    float sg0;
    const bool uni = sigma_uniform(sigma, sg0);
    const float q0  = -0.72134752044448170f * ex2f(-2.0f * sg0 * 1.4426950408889634f);
    const float scl = uni ? sqrtf(-q0) : 1.0f;

    const float* yb = y + (size_t)b * NOBS * CCH;
    uint4 bf;
    bf.x = packh2(yb[(k0 + 2*q) * CCH + c],         yb[(k0 + 2*q + 1) * CCH + c]);
    bf.y = packh2(yb[(k0 + 8 + 2*q) * CCH + c],     yb[(k0 + 9 + 2*q) * CCH + c]);
    bf.z = packh2(yb[(k0 + 2*q) * CCH + c + 8],     yb[(k0 + 2*q + 1) * CCH + c + 8]);
    bf.w = packh2(yb[(k0 + 8 + 2*q) * CCH + c + 8], yb[(k0 + 9 + 2*q) * CCH + c + 8]);
    g_bf[b][kt][l] = bf;

    const float* xb = x + b * NOBS;
    g_xf[b][kt][l] = make_float4(scl * xb[k0 + 2*q],     scl * xb[k0 + 2*q + 1],
                                 scl * xb[k0 + 8 + 2*q], scl * xb[k0 + 9 + 2*q]);
}

// ---- kernel 2: mainloop from fragments; deep batched prefetch ----
__global__ __launch_bounds__(THREADS, 3) void setconv_mma_kernel(
    const float* __restrict__ x, const float* __restrict__ y,
    const float* __restrict__ t, const float* __restrict__ sigma,
    const float* __restrict__ W, const float* __restrict__ bias,
    float* __restrict__ out)
{
    __shared__ float sred[KSPLIT][M_B][CCH];   // 8 KB
    __shared__ float yout[M_B][CCH + 1];
    __shared__ float sWt[CCH][OCH];
    __shared__ float sb[OCH];

    const int tid  = threadIdx.x;
    const int warp = tid >> 5, lane = tid & 31;
    const int b  = blockIdx.x / MTILES;
    const int mt = blockIdx.x % MTILES;
    const int mbase = mt * M_B;
    const int ks = warp;                 // k-split 0..7, 8 ktiles each

    for (int i = tid; i < OCH * CCH; i += THREADS) {
        int o = i / CCH, c = i % CCH;
        sWt[c][o] = W[i];
    }
    if (tid < OCH) sb[tid] = bias[tid];

    float sg0;
    const bool uniform = sigma_uniform(sigma, sg0);
    const float q0  = -0.72134752044448170f * ex2f(-2.0f * sg0 * 1.4426950408889634f);
    const float scl = sqrtf(-q0);

    if (uniform) {
        const int g = lane >> 2;         // 0..7
        const float t0 = scl * t[b * MOUT + mbase + g];
        const float t1 = scl * t[b * MOUT + mbase + g + 8];

        float c00 = 0.f, c01 = 0.f, c02 = 0.f, c03 = 0.f;   // ch0-7
        float c10 = 0.f, c11 = 0.f, c12 = 0.f, c13 = 0.f;   // ch8-15

        const uint4*  bfp = &g_bf[b][ks * KT_PER_WARP][lane];
        const float4* xfp = &g_xf[b][ks * KT_PER_WARP][lane];

        uint4  bf[2][CHUNK];
        float4 xf[2][CHUNK];
        // prologue: burst-load chunk 0 (8 LDG.128 in flight)
        #pragma unroll
        for (int j = 0; j < CHUNK; j++) {
            bf[0][j] = bfp[j * 32];
            xf[0][j] = xfp[j * 32];
        }

        #pragma unroll
        for (int ch = 0; ch < NCHUNKS; ch++) {
            const int cur = ch & 1, nxt = cur ^ 1;
            if (ch + 1 < NCHUNKS) {
                #pragma unroll
                for (int j = 0; j < CHUNK; j++) {
                    bf[nxt][j] = bfp[((ch + 1) * CHUNK + j) * 32];
                    xf[nxt][j] = xfp[((ch + 1) * CHUNK + j) * 32];
                }
            }
            #pragma unroll
            for (int j = 0; j < CHUNK; j++) {
                const float4 xv = xf[cur][j];
                float d;
                d = xv.x - t0; const float w00 = ex2f(-d * d);
                d = xv.y - t0; const float w01 = ex2f(-d * d);
                d = xv.x - t1; const float w10 = ex2f(-d * d);
                d = xv.y - t1; const float w11 = ex2f(-d * d);
                d = xv.z - t0; const float w02 = ex2f(-d * d);
                d = xv.w - t0; const float w03 = ex2f(-d * d);
                d = xv.z - t1; const float w12 = ex2f(-d * d);
                d = xv.w - t1; const float w13 = ex2f(-d * d);

                const uint32_t a0 = packh2(w00, w01);
                const uint32_t a1 = packh2(w10, w11);
                const uint32_t a2 = packh2(w02, w03);
                const uint32_t a3 = packh2(w12, w13);

                mma16816(c00, c01, c02, c03, a0, a1, a2, a3, bf[cur][j].x, bf[cur][j].y);
                mma16816(c10, c11, c12, c13, a0, a1, a2, a3, bf[cur][j].z, bf[cur][j].w);
            }
        }

        const int tq = lane & 3;
        const int col0 = 2 * tq;
        *(float2*)&sred[ks][g][col0]          = make_float2(c00, c01);
        *(float2*)&sred[ks][g + 8][col0]      = make_float2(c02, c03);
        *(float2*)&sred[ks][g][8 + col0]      = make_float2(c10, c11);
        *(float2*)&sred[ks][g + 8][8 + col0]  = make_float2(c12, c13);
    } else {
        // ---- general per-channel-sigma fallback (slow, correct; global reads) ----
        float q[CCH];
        #pragma unroll
        for (int c = 0; c < CCH; c++)
            q[c] = -0.72134752044448170f * ex2f(-2.0f * sigma[c] * 1.4426950408889634f);
        const int ml = lane & 15;
        const int half = lane >> 4;
        const float tm = t[b * MOUT + mbase + ml];
        float acc[CCH];
        #pragma unroll
        for (int c = 0; c < CCH; c++) acc[c] = 0.0f;
        const int n0 = ks * (NOBS / KSPLIT);
        for (int nn = n0 + half; nn < n0 + NOBS / KSPLIT; nn += 2) {
            const float xv = x[b * NOBS + nn];
            const float dd = (xv - tm) * (xv - tm);
            const float* yr = y + ((size_t)b * NOBS + nn) * CCH;
            #pragma unroll
            for (int c = 0; c < CCH; c++)
                acc[c] += ex2f(q[c] * dd) * yr[c];
        }
        #pragma unroll
        for (int c = 0; c < CCH; c++)
            acc[c] += __shfl_xor_sync(0xffffffffu, acc[c], 16);
        if (half == 0)
            #pragma unroll
            for (int c = 0; c < CCH; c++) sred[ks][ml][c] = acc[c];
    }

    __syncthreads();

    // ---- reduce 8 k-splits -> yout (256 sums; 1 per thread) ----
    {
        const int m = tid >> 4;        // 0..15
        const int c = tid & 15;
        float s = 0.0f;
        #pragma unroll
        for (int k = 0; k < KSPLIT; k++) s += sred[k][m][c];
        yout[m][c] = s;
    }
    __syncthreads();

    // ---- 16->32 linear: thread = (o, m-pair); 2 m per thread, coalesced ----
    {
        const int o  = tid & 31;        // distinct per lane
        const int mg = tid >> 5;        // 0..7, constant within warp
        const float bv = sb[o];
        float wv[CCH];
        #pragma unroll
        for (int c = 0; c < CCH; c++) wv[c] = sWt[c][o];
        #pragma unroll
        for (int j = 0; j < 2; j++) {
            const int m = mg * 2 + j;
            float a = bv;
            #pragma unroll
            for (int c = 0; c < CCH; c++) a += yout[m][c] * wv[c];
            out[((size_t)b * MOUT + mbase + m) * OCH + o] = a;
        }
    }
}

extern "C" void kernel_launch(void* const* d_in, const int* in_sizes, int n_in,
                              void* d_out, int out_size)
{
    const float* x     = (const float*)d_in[0];
    const float* y     = (const float*)d_in[1];
    const float* t     = (const float*)d_in[2];
    const float* sigma = (const float*)d_in[3];
    const float* W     = (const float*)d_in[4];
    const float* bias  = (const float*)d_in[5];
    float* out = (float*)d_out;

    build_frags<<<BATCH * KTG * 32 / 256, 256>>>(x, y, sigma);
    setconv_mma_kernel<<<BATCH * MTILES, THREADS>>>(x, y, t, sigma, W, bias, out);
}

// round 17
// speedup vs baseline: 1.3975x; 1.1957x over previous
#include <cuda_runtime.h>
#include <cuda_fp16.h>
#include <cstdint>
#include <math.h>

#define BATCH 8
#define NOBS 1024
#define MOUT 1024
#define CCH 16
#define OCH 32
#define THREADS 256              // 8 warps per block
#define M_B 32                   // m per block (32 per warp via 2 A-fragments)
#define MTILES (MOUT / M_B)      // 32 -> grid 256
#define KSPLIT 8
#define KTG 64                   // global k-tiles of 16 obs
#define KT_PER_WARP (KTG / KSPLIT)  // 8
#define CHUNK 2                  // k-tiles per load burst
#define NCHUNKS (KT_PER_WARP / CHUNK) // 4

// Precomputed MMA fragments (written by build_frags, read by main kernel)
__device__ uint4  g_bf[BATCH][KTG][32];   // B fragments: y as f16, 256 KB
__device__ float4 g_xf[BATCH][KTG][32];   // x values per lane, 256 KB

__device__ __forceinline__ float ex2f(float v) {
    float r; asm("ex2.approx.ftz.f32 %0, %1;" : "=f"(r) : "f"(v)); return r;
}
__device__ __forceinline__ uint32_t packh2(float lo, float hi) {
    uint32_t r; asm("cvt.rn.f16x2.f32 %0, %1, %2;" : "=r"(r) : "f"(hi), "f"(lo)); return r;
}
__device__ __forceinline__ void mma16816(float& c0, float& c1, float& c2, float& c3,
                                         uint32_t a0, uint32_t a1, uint32_t a2, uint32_t a3,
                                         uint32_t b0, uint32_t b1) {
    asm volatile("mma.sync.aligned.m16n8k16.row.col.f32.f16.f16.f32 "
                 "{%0,%1,%2,%3}, {%4,%5,%6,%7}, {%8,%9}, {%0,%1,%2,%3};"
                 : "+f"(c0), "+f"(c1), "+f"(c2), "+f"(c3)
                 : "r"(a0), "r"(a1), "r"(a2), "r"(a3), "r"(b0), "r"(b1));
}

__device__ __forceinline__ bool sigma_uniform(const float* sigma, float& sg0) {
    sg0 = sigma[0];
    bool u = true;
    #pragma unroll
    for (int c = 1; c < CCH; c++) u &= (sigma[c] == sg0);
    return u;
}

// ---- kernel 1: build fragments; bf and xf built by disjoint thread ranges ----
__global__ __launch_bounds__(256) void build_frags(
    const float* __restrict__ x, const float* __restrict__ y,
    const float* __restrict__ sigma)
{
    const int gidx = blockIdx.x * 256 + threadIdx.x;   // 0..32767
    const int idx  = gidx & 16383;
    const int b  = idx >> 11;
    const int kt = (idx >> 5) & (KTG - 1);
    const int l  = idx & 31;
    const int q  = l & 3, c = l >> 2;
    const int k0 = kt * 16;

    if (gidx < 16384) {
        // B fragment: y -> f16, m16n8k16 col-major layout
        const float* yb = y + (size_t)b * NOBS * CCH;
        uint4 bf;
        bf.x = packh2(yb[(k0 + 2*q) * CCH + c],         yb[(k0 + 2*q + 1) * CCH + c]);
        bf.y = packh2(yb[(k0 + 8 + 2*q) * CCH + c],     yb[(k0 + 9 + 2*q) * CCH + c]);
        bf.z = packh2(yb[(k0 + 2*q) * CCH + c + 8],     yb[(k0 + 2*q + 1) * CCH + c + 8]);
        bf.w = packh2(yb[(k0 + 8 + 2*q) * CCH + c + 8], yb[(k0 + 9 + 2*q) * CCH + c + 8]);
        g_bf[b][kt][l] = bf;
    } else {
        float sg0;
        const bool uni = sigma_uniform(sigma, sg0);
        const float q0  = -0.72134752044448170f * ex2f(-2.0f * sg0 * 1.4426950408889634f);
        const float scl = uni ? sqrtf(-q0) : 1.0f;
        const float* xb = x + b * NOBS;
        g_xf[b][kt][l] = make_float4(scl * xb[k0 + 2*q],     scl * xb[k0 + 2*q + 1],
                                     scl * xb[k0 + 8 + 2*q], scl * xb[k0 + 9 + 2*q]);
    }
}

// ---- kernel 2: 32m/warp mainloop from fragments; PDL-overlapped ----
__global__ __launch_bounds__(THREADS, 2) void setconv_mma_kernel(
    const float* __restrict__ x, const float* __restrict__ y,
    const float* __restrict__ t, const float* __restrict__ sigma,
    const float* __restrict__ W, const float* __restrict__ bias,
    float* __restrict__ out)
{
    __shared__ float sred[KSPLIT][M_B][CCH];   // 16 KB
    __shared__ float yout[M_B][CCH + 1];
    __shared__ float sWt[CCH][OCH];
    __shared__ float sb[OCH];

    const int tid  = threadIdx.x;
    const int warp = tid >> 5, lane = tid & 31;
    const int b  = blockIdx.x / MTILES;
    const int mt = blockIdx.x % MTILES;
    const int mbase = mt * M_B;
    const int ks = warp;                 // k-split 0..7, 8 ktiles each

    // prologue (overlaps prep kernel under PDL): W, bias, t, sigma
    for (int i = tid; i < OCH * CCH; i += THREADS) {
        int o = i / CCH, c = i % CCH;
        sWt[c][o] = W[i];
    }
    if (tid < OCH) sb[tid] = bias[tid];

    float sg0;
    const bool uniform = sigma_uniform(sigma, sg0);
    const float q0  = -0.72134752044448170f * ex2f(-2.0f * sg0 * 1.4426950408889634f);
    const float scl = sqrtf(-q0);

    const int g = lane >> 2;             // 0..7
    const float t0 = scl * t[b * MOUT + mbase + g];
    const float t1 = scl * t[b * MOUT + mbase + g + 8];
    const float t2 = scl * t[b * MOUT + mbase + 16 + g];
    const float t3 = scl * t[b * MOUT + mbase + 24 + g];

    // wait for prep kernel's fragment writes to be visible
    asm volatile("griddepcontrol.wait;" ::: "memory");

    if (uniform) {
        float c00 = 0.f, c01 = 0.f, c02 = 0.f, c03 = 0.f;   // frag0 ch0-7
        float c10 = 0.f, c11 = 0.f, c12 = 0.f, c13 = 0.f;   // frag0 ch8-15
        float c20 = 0.f, c21 = 0.f, c22 = 0.f, c23 = 0.f;   // frag1 ch0-7
        float c30 = 0.f, c31 = 0.f, c32 = 0.f, c33 = 0.f;   // frag1 ch8-15

        const uint4*  bfp = &g_bf[b][ks * KT_PER_WARP][lane];
        const float4* xfp = &g_xf[b][ks * KT_PER_WARP][lane];

        uint4  bf[2][CHUNK];
        float4 xf[2][CHUNK];
        #pragma unroll
        for (int j = 0; j < CHUNK; j++) {
            bf[0][j] = bfp[j * 32];
            xf[0][j] = xfp[j * 32];
        }

        #pragma unroll
        for (int ch = 0; ch < NCHUNKS; ch++) {
            const int cur = ch & 1, nxt = cur ^ 1;
            if (ch + 1 < NCHUNKS) {
                #pragma unroll
                for (int j = 0; j < CHUNK; j++) {
                    bf[nxt][j] = bfp[((ch + 1) * CHUNK + j) * 32];
                    xf[nxt][j] = xfp[((ch + 1) * CHUNK + j) * 32];
                }
            }
            #pragma unroll
            for (int j = 0; j < CHUNK; j++) {
                const float4 xv = xf[cur][j];
                float d;
                // fragment 0 (t0, t1)
                d = xv.x - t0; const float w00 = ex2f(-d * d);
                d = xv.y - t0; const float w01 = ex2f(-d * d);
                d = xv.x - t1; const float w10 = ex2f(-d * d);
                d = xv.y - t1; const float w11 = ex2f(-d * d);
                d = xv.z - t0; const float w02 = ex2f(-d * d);
                d = xv.w - t0; const float w03 = ex2f(-d * d);
                d = xv.z - t1; const float w12 = ex2f(-d * d);
                d = xv.w - t1; const float w13 = ex2f(-d * d);
                const uint32_t a0 = packh2(w00, w01);
                const uint32_t a1 = packh2(w10, w11);
                const uint32_t a2 = packh2(w02, w03);
                const uint32_t a3 = packh2(w12, w13);
                mma16816(c00, c01, c02, c03, a0, a1, a2, a3, bf[cur][j].x, bf[cur][j].y);
                mma16816(c10, c11, c12, c13, a0, a1, a2, a3, bf[cur][j].z, bf[cur][j].w);

                // fragment 1 (t2, t3) — same x, same B
                d = xv.x - t2; const float v00 = ex2f(-d * d);
                d = xv.y - t2; const float v01 = ex2f(-d * d);
                d = xv.x - t3; const float v10 = ex2f(-d * d);
                d = xv.y - t3; const float v11 = ex2f(-d * d);
                d = xv.z - t2; const float v02 = ex2f(-d * d);
                d = xv.w - t2; const float v03 = ex2f(-d * d);
                d = xv.z - t3; const float v12 = ex2f(-d * d);
                d = xv.w - t3; const float v13 = ex2f(-d * d);
                const uint32_t e0 = packh2(v00, v01);
                const uint32_t e1 = packh2(v10, v11);
                const uint32_t e2 = packh2(v02, v03);
                const uint32_t e3 = packh2(v12, v13);
                mma16816(c20, c21, c22, c23, e0, e1, e2, e3, bf[cur][j].x, bf[cur][j].y);
                mma16816(c30, c31, c32, c33, e0, e1, e2, e3, bf[cur][j].z, bf[cur][j].w);
            }
        }

        const int tq = lane & 3;
        const int col0 = 2 * tq;
        *(float2*)&sred[ks][g][col0]           = make_float2(c00, c01);
        *(float2*)&sred[ks][g + 8][col0]       = make_float2(c02, c03);
        *(float2*)&sred[ks][g][8 + col0]       = make_float2(c10, c11);
        *(float2*)&sred[ks][g + 8][8 + col0]   = make_float2(c12, c13);
        *(float2*)&sred[ks][16 + g][col0]      = make_float2(c20, c21);
        *(float2*)&sred[ks][24 + g][col0]      = make_float2(c22, c23);
        *(float2*)&sred[ks][16 + g][8 + col0]  = make_float2(c30, c31);
        *(float2*)&sred[ks][24 + g][8 + col0]  = make_float2(c32, c33);
    } else {
        // ---- general per-channel-sigma fallback (slow, correct; global reads) ----
        float q[CCH];
        #pragma unroll
        for (int c = 0; c < CCH; c++)
            q[c] = -0.72134752044448170f * ex2f(-2.0f * sigma[c] * 1.4426950408889634f);
        const float tm = t[b * MOUT + mbase + lane];   // lane = m (0..31)
        float acc[CCH];
        #pragma unroll
        for (int c = 0; c < CCH; c++) acc[c] = 0.0f;
        const int n0 = ks * (NOBS / KSPLIT);
        for (int nn = n0; nn < n0 + NOBS / KSPLIT; nn++) {
            const float xv = x[b * NOBS + nn];
            const float dd = (xv - tm) * (xv - tm);
            const float* yr = y + ((size_t)b * NOBS + nn) * CCH;
            #pragma unroll
            for (int c = 0; c < CCH; c++)
                acc[c] += ex2f(q[c] * dd) * yr[c];
        }
        #pragma unroll
        for (int c = 0; c < CCH; c++) sred[ks][lane][c] = acc[c];
    }

    __syncthreads();

    // ---- reduce 8 k-splits -> yout (512 sums; 2 per thread) ----
    #pragma unroll
    for (int r = 0; r < 2; r++) {
        const int idx = tid + THREADS * r;   // 0..511
        const int m = idx >> 4;
        const int c = idx & 15;
        float s = 0.0f;
        #pragma unroll
        for (int k = 0; k < KSPLIT; k++) s += sred[k][m][c];
        yout[m][c] = s;
    }
    __syncthreads();

    // ---- 16->32 linear: thread = (o, m-group); 4 m per thread, coalesced ----
    {
        const int o  = tid & 31;        // distinct per lane
        const int mg = tid >> 5;        // 0..7, constant within warp
        const float bv = sb[o];
        float wv[CCH];
        #pragma unroll
        for (int c = 0; c < CCH; c++) wv[c] = sWt[c][o];
        #pragma unroll
        for (int j = 0; j < 4; j++) {
            const int m = mg * 4 + j;
            float a = bv;
            #pragma unroll
            for (int c = 0; c < CCH; c++) a += yout[m][c] * wv[c];
            out[((size_t)b * MOUT + mbase + m) * OCH + o] = a;
        }
    }
}

extern "C" void kernel_launch(void* const* d_in, const int* in_sizes, int n_in,
                              void* d_out, int out_size)
{
    const float* x     = (const float*)d_in[0];
    const float* y     = (const float*)d_in[1];
    const float* t     = (const float*)d_in[2];
    const float* sigma = (const float*)d_in[3];
    const float* W     = (const float*)d_in[4];
    const float* bias  = (const float*)d_in[5];
    float* out = (float*)d_out;

    build_frags<<<128, 256>>>(x, y, sigma);

    // PDL launch: main starts while build_frags runs; griddepcontrol.wait
    // inside the kernel orders fragment reads after prep completion.
    cudaLaunchConfig_t cfg = {};
    cfg.gridDim  = dim3(BATCH * MTILES, 1, 1);
    cfg.blockDim = dim3(THREADS, 1, 1);
    cudaLaunchAttribute attrs[1];
    attrs[0].id = cudaLaunchAttributeProgrammaticStreamSerialization;
    attrs[0].val.programmaticStreamSerializationAllowed = 1;
    cfg.attrs = attrs;
    cfg.numAttrs = 1;
    cudaError_t err = cudaLaunchKernelEx(&cfg, setconv_mma_kernel,
                                         x, y, t, sigma, W, bias, out);
    if (err != cudaSuccess) {
        // fallback: plain launch (griddepcontrol.wait is benign under stream order)
        setconv_mma_kernel<<<BATCH * MTILES, THREADS>>>(x, y, t, sigma, W, bias, out);
    }
}